// round 13
// baseline (speedup 1.0000x reference)
#include <cuda_runtime.h>
#include <math.h>

#define S_LEN    4096
#define B_SZ     8
#define HID      768
#define HS_DIM   256   // HIDDEN/3
#define NFREQ    384   // HID/2
#define HS_NFREQ 128   // HS_DIM/2

typedef unsigned long long u64;

// ---------------------------------------------------------------------------
// Packed f32x2 helpers (sm_103a FADD2/FFMA2; .rn => bit-identical to scalar)
// ---------------------------------------------------------------------------
__device__ __forceinline__ u64 pk2(float lo, float hi) {
    u64 r; asm("mov.b64 %0, {%1, %2};" : "=l"(r) : "f"(lo), "f"(hi)); return r;
}
__device__ __forceinline__ void upk2(u64 v, float& lo, float& hi) {
    asm("mov.b64 {%0, %1}, %2;" : "=f"(lo), "=f"(hi) : "l"(v));
}
__device__ __forceinline__ u64 add2(u64 a, u64 b) {
    u64 r; asm("add.rn.f32x2 %0, %1, %2;" : "=l"(r) : "l"(a), "l"(b)); return r;
}
__device__ __forceinline__ u64 mul2(u64 a, u64 b) {
    u64 r; asm("mul.rn.f32x2 %0, %1, %2;" : "=l"(r) : "l"(a), "l"(b)); return r;
}
__device__ __forceinline__ u64 fma2(u64 a, u64 b, u64 c) {
    u64 r; asm("fma.rn.f32x2 %0, %1, %2, %3;" : "=l"(r) : "l"(a), "l"(b), "l"(c)); return r;
}

// ---------------------------------------------------------------------------
// Compile-time exp: double-precision range reduction + Taylor, evaluated by
// the host compiler. Result rounded to float = correctly-rounded exp of the
// f32 argument (>= expf accuracy). Args are all in [-9.2, 0].
// ---------------------------------------------------------------------------
constexpr double cexp_d(double x) {
    const double LN2 = 0.6931471805599453094172321214582;
    double q = x / LN2;
    int n = (int)(q - 0.5);              // round-to-nearest for q <= 0
    double r = x - (double)n * LN2;
    double term = 1.0, sum = 1.0;
    for (int i = 1; i < 24; i++) { term *= r / (double)i; sum += term; }
    double sc = 1.0;
    for (int i = 0; i < -n; i++) sc *= 0.5;   // n <= 0 for our args
    return sum * sc;
}
struct TabPE { float v[NFREQ]; };
struct TabHS { float v[HS_NFREQ]; };
constexpr TabPE make_pe_div() {
    TabPE t{};
    const float CEXP = (float)(-9.210340371976184 / 768.0);  // -ln(1e4)/HID
    for (int k = 0; k < NFREQ; k++) {
        float arg = (float)(2 * k) * CEXP;                   // f32 like jax
        t.v[k] = (float)cexp_d((double)arg);
    }
    return t;
}
constexpr TabHS make_hs_div() {
    TabHS t{};
    const float CEXP = (float)(-9.210340371976184 / 256.0);  // -ln(1e4)/HS_DIM
    for (int k = 0; k < HS_NFREQ; k++) {
        float arg = (float)(2 * k) * CEXP;
        t.v[k] = (float)cexp_d((double)arg);
    }
    return t;
}
__device__ const TabPE g_pe_div = make_pe_div();
__device__ const TabHS g_hs_div = make_hs_div();

// ---------------------------------------------------------------------------
// Accurate sincos for |ang| up to ~5000: 3-term Cody-Waite 2*pi reduction
// then MUFU sincos.
// ---------------------------------------------------------------------------
__device__ __forceinline__ void sincos_red(float ang, float* s, float* c) {
    const double TWO_PI_D = 6.283185307179586476925286766559;
    const float  P1 = 6.28125f;
    const float  P2 = (float)(TWO_PI_D - (double)6.28125f);
    const float  P3 = (float)(TWO_PI_D - (double)6.28125f - (double)((float)(TWO_PI_D - (double)6.28125f)));
    const float  INV2PI = 0.15915494309189535f;
    float k = rintf(ang * INV2PI);
    float r = fmaf(-k, P1, ang);
    r = fmaf(-k, P2, r);
    r = fmaf(-k, P3, r);
    __sincosf(r, s, c);
}

// ---------------------------------------------------------------------------
// SINGLE fused kernel: CTA = one position s, 384 threads, ALL 8 batch rows.
// half h = tid/192 owns rows 4h..4h+3; column c = tid%192 (float4).
//   - word rows: 4 independent LDG.128 issued FIRST
//   - pe: ONE sincos per thread (freq k=tid, div from compile-time table)
//     into SMEM -- pe trig now computed once per position, not twice
//   - hs: 8 rows x 128 pairs cooperatively into SMEM (2.67 sincos/thread),
//     divs from compile-time table (zero expf anywhere)
//   - all elementwise math packed f32x2
// ---------------------------------------------------------------------------
#define RED_ROUND(OFF, K)                                                   \
    {                                                                       \
        _Pragma("unroll")                                                   \
        for (int j = 0; j < (K) / 2; j++) {                                 \
            float send = (lane & (OFF)) ? vals[j] : vals[j + (K) / 2];      \
            float recv = __shfl_xor_sync(0xffffffffu, send, (OFF));         \
            float keep = (lane & (OFF)) ? vals[j + (K) / 2] : vals[j];      \
            vals[j] = keep + recv;                                          \
        }                                                                   \
    }

__global__ __launch_bounds__(384, 3) void emb_ln_kernel(
    const int*   __restrict__ input_ids,     // [8,4096]
    const int*   __restrict__ tok_struct,    // [8,4096,3]
    const int*   __restrict__ token_type,    // [8,4096]
    const float* __restrict__ word_emb,      // [30522,768]
    const float* __restrict__ type_emb,      // [2,768]
    const float* __restrict__ ln_w,          // [768]
    const float* __restrict__ ln_b,          // [768]
    float*       __restrict__ out)           // [8,4096,768]
{
    __shared__ __align__(16) float s_pe[HID];          // 3KB: pe[s] row
    __shared__ __align__(16) float s_hs[8 * HS_DIM];   // 8KB: 8 hs rows
    __shared__ float s_red[12 * 8];
    __shared__ float s_mu[8], s_rstd[8];
    __shared__ int   s_pp[8];

    const int s    = blockIdx.x;
    const int tid  = threadIdx.x;
    const int warp = tid >> 5;
    const int lane = tid & 31;
    const int h    = (tid >= 192) ? 1 : 0;   // half: rows 4h..4h+3
    const int c    = tid - h * 192;          // float4 column 0..191
    const int hc   = c & 63;                 // hs float4 column (concat(g,g,g))

    // para_pos for all 8 rows -> smem (needed by the cooperative hs loop)
    if (tid < 8) s_pp[tid] = __ldg(&tok_struct[(tid * S_LEN + s) * 3]);

    // Row metadata for this half's 4 rows: lanes 0..3 load, broadcast by shfl.
    int myTok = 0, myTT = 0;
    if (lane < 4) {
        int idx = (h * 4 + lane) * S_LEN + s;
        myTok = __ldg(&input_ids[idx]);
        myTT  = __ldg(&token_type[idx]);
    }

    // Issue the 4 word-row gathers NOW so their latency overlaps all the trig.
    const float4* w4p = (const float4*)word_emb;
    float4 wv[4];
#pragma unroll
    for (int r = 0; r < 4; r++) {
        int tok = __shfl_sync(0xffffffffu, myTok, r);
        wv[r] = __ldg(w4p + (size_t)tok * 192 + c);
    }

    // Type rows (L1-hot) before the barrier.
    const float4 t0 = __ldg(((const float4*)type_emb) + c);
    const float4 t1 = __ldg(((const float4*)type_emb) + 192 + c);

    __syncthreads();                         // s_pp visible

    // pe: one freq per thread (k = tid, 384 freqs total)
    {
        float d = __ldg(&g_pe_div.v[tid]);
        float sv, cv;
        sincos_red((float)s * d, &sv, &cv);
        s_pe[2 * tid]     = sv;
        s_pe[2 * tid + 1] = cv;
    }

    // hs: 8 rows x 128 freq pairs = 1024 tasks over 384 threads
#pragma unroll
    for (int t = tid; t < 8 * HS_NFREQ; t += 384) {
        int r8 = t >> 7;
        int k  = t & 127;
        float d = __ldg(&g_hs_div.v[k]);
        float sv, cv;
        sincos_red((float)s_pp[r8] * d, &sv, &cv);
        ((float2*)s_hs)[t] = make_float2(sv, cv);
    }

    __syncthreads();                         // s_pe, s_hs ready

    // pe + type prefolded into packed pairs
    const float4 pe4 = ((const float4*)s_pe)[c];
    const u64 pe01 = pk2(pe4.x, pe4.y), pe23 = pk2(pe4.z, pe4.w);
    const u64 pt0_01 = add2(pe01, pk2(t0.x, t0.y));
    const u64 pt0_23 = add2(pe23, pk2(t0.z, t0.w));
    const u64 pt1_01 = add2(pe01, pk2(t1.x, t1.y));
    const u64 pt1_23 = add2(pe23, pk2(t1.z, t1.w));

    u64   e01[4], e23[4];
    float vals[8];                           // [sum0..3, sq0..3]
#pragma unroll
    for (int r = 0; r < 4; r++) {
        int tt = __shfl_sync(0xffffffffu, myTT, r);
        float4 h4 = ((const float4*)s_hs)[(h * 4 + r) * 64 + hc];
        u64 p01 = tt ? pt1_01 : pt0_01;
        u64 p23 = tt ? pt1_23 : pt0_23;
        u64 w01 = pk2(wv[r].x, wv[r].y);
        u64 w23 = pk2(wv[r].z, wv[r].w);
        u64 a01 = add2(add2(w01, pk2(h4.x, h4.y)), p01);
        u64 a23 = add2(add2(w23, pk2(h4.z, h4.w)), p23);
        e01[r] = a01;
        e23[r] = a23;
        float sl, sh, ql, qh;
        upk2(add2(a01, a23), sl, sh);
        vals[r] = sl + sh;
        upk2(fma2(a23, a23, mul2(a01, a01)), ql, qh);
        vals[4 + r] = ql + qh;
    }

    // Value-splitting butterfly: 8 values over 32 lanes.
    RED_ROUND(16, 8)
    RED_ROUND(8, 4)
    RED_ROUND(4, 2)
    vals[0] += __shfl_xor_sync(0xffffffffu, vals[0], 2);
    vals[0] += __shfl_xor_sync(0xffffffffu, vals[0], 1);
    if ((lane & 3) == 0) s_red[warp * 8 + (lane >> 2)] = vals[0];
    __syncthreads();

    if (tid < 8) {
        int hh = tid >> 2, rr = tid & 3;
        float sum = 0.f, sq = 0.f;
#pragma unroll
        for (int w = 0; w < 6; w++) {
            sum += s_red[(hh * 6 + w) * 8 + rr];
            sq  += s_red[(hh * 6 + w) * 8 + 4 + rr];
        }
        const float inv_n = 1.0f / 768.0f;
        float mu  = sum * inv_n;
        float var = fmaf(sq, inv_n, -mu * mu);
        var = var < 0.f ? 0.f : var;
        s_mu[tid]   = mu;
        s_rstd[tid] = rsqrtf(var + 1e-12f);
    }
    __syncthreads();

    // ln params loaded after the barrier: not live across the gather loop.
    const float4 wgf = __ldg(((const float4*)ln_w) + c);
    const float4 bif = __ldg(((const float4*)ln_b) + c);
    const u64 wg01 = pk2(wgf.x, wgf.y), wg23 = pk2(wgf.z, wgf.w);
    const u64 bi01 = pk2(bif.x, bif.y), bi23 = pk2(bif.z, bif.w);

    float4* o4 = (float4*)out;
#pragma unroll
    for (int r = 0; r < 4; r++) {
        int R = h * 4 + r;
        float mu   = s_mu[R];
        float rstd = s_rstd[R];
        u64 rstd2 = pk2(rstd, rstd);
        u64 nmu2  = pk2(-mu, -mu);
        u64 a01 = mul2(wg01, rstd2);            // wg * rstd
        u64 a23 = mul2(wg23, rstd2);
        u64 b01 = fma2(nmu2, a01, bi01);        // bi - mu*wg*rstd
        u64 b23 = fma2(nmu2, a23, bi23);
        u64 q01 = fma2(e01[r], a01, b01);       // e*(wg*rstd) + b
        u64 q23 = fma2(e23[r], a23, b23);
        float4 o;
        upk2(q01, o.x, o.y);
        upk2(q23, o.z, o.w);
        __stcs(o4 + (size_t)(R * S_LEN + s) * 192 + c, o);
    }
}

// ---------------------------------------------------------------------------
extern "C" void kernel_launch(void* const* d_in, const int* in_sizes, int n_in,
                              void* d_out, int out_size) {
    const int*   input_ids  = (const int*)  d_in[0];
    const int*   tok_struct = (const int*)  d_in[1];
    // d_in[2] = sent_struct_vec (unused by the reference output)
    const int*   token_type = (const int*)  d_in[3];
    const float* word_emb   = (const float*)d_in[4];
    const float* type_emb   = (const float*)d_in[5];
    const float* ln_w       = (const float*)d_in[6];
    const float* ln_b       = (const float*)d_in[7];
    float*       out        = (float*)d_out;

    emb_ln_kernel<<<S_LEN, 384>>>(input_ids, tok_struct, token_type,
                                  word_emb, type_emb, ln_w, ln_b, out);
}

// round 14
// speedup vs baseline: 1.1020x; 1.1020x over previous
#include <cuda_runtime.h>
#include <math.h>

#define S_LEN    4096
#define B_SZ     8
#define HID      768
#define HS_DIM   256   // HIDDEN/3
#define NFREQ    384   // HID/2
#define HS_NFREQ 128   // HS_DIM/2

typedef unsigned long long u64;

// ---------------------------------------------------------------------------
// Packed f32x2 helpers (sm_103a FADD2/FFMA2; .rn => bit-identical to scalar)
// ---------------------------------------------------------------------------
__device__ __forceinline__ u64 pk2(float lo, float hi) {
    u64 r; asm("mov.b64 %0, {%1, %2};" : "=l"(r) : "f"(lo), "f"(hi)); return r;
}
__device__ __forceinline__ void upk2(u64 v, float& lo, float& hi) {
    asm("mov.b64 {%0, %1}, %2;" : "=f"(lo), "=f"(hi) : "l"(v));
}
__device__ __forceinline__ u64 add2(u64 a, u64 b) {
    u64 r; asm("add.rn.f32x2 %0, %1, %2;" : "=l"(r) : "l"(a), "l"(b)); return r;
}
__device__ __forceinline__ u64 mul2(u64 a, u64 b) {
    u64 r; asm("mul.rn.f32x2 %0, %1, %2;" : "=l"(r) : "l"(a), "l"(b)); return r;
}
__device__ __forceinline__ u64 fma2(u64 a, u64 b, u64 c) {
    u64 r; asm("fma.rn.f32x2 %0, %1, %2, %3;" : "=l"(r) : "l"(a), "l"(b), "l"(c)); return r;
}

// ---------------------------------------------------------------------------
// Compile-time exp: double-precision range reduction + Taylor, evaluated by
// the host compiler. Result rounded to float = correctly-rounded exp of the
// f32 argument (>= expf accuracy). Args are all in [-9.2, 0].
// ---------------------------------------------------------------------------
constexpr double cexp_d(double x) {
    const double LN2 = 0.6931471805599453094172321214582;
    double q = x / LN2;
    int n = (int)(q - 0.5);              // round-to-nearest for q <= 0
    double r = x - (double)n * LN2;
    double term = 1.0, sum = 1.0;
    for (int i = 1; i < 24; i++) { term *= r / (double)i; sum += term; }
    double sc = 1.0;
    for (int i = 0; i < -n; i++) sc *= 0.5;   // n <= 0 for our args
    return sum * sc;
}
struct TabPE { float v[NFREQ]; };
struct TabHS { float v[HS_NFREQ]; };
constexpr TabPE make_pe_div() {
    TabPE t{};
    const float CEXP = (float)(-9.210340371976184 / 768.0);  // -ln(1e4)/HID
    for (int k = 0; k < NFREQ; k++) {
        float arg = (float)(2 * k) * CEXP;                   // f32 like jax
        t.v[k] = (float)cexp_d((double)arg);
    }
    return t;
}
constexpr TabHS make_hs_div() {
    TabHS t{};
    const float CEXP = (float)(-9.210340371976184 / 256.0);  // -ln(1e4)/HS_DIM
    for (int k = 0; k < HS_NFREQ; k++) {
        float arg = (float)(2 * k) * CEXP;
        t.v[k] = (float)cexp_d((double)arg);
    }
    return t;
}
__device__ const TabPE g_pe_div = make_pe_div();
__device__ const TabHS g_hs_div = make_hs_div();

// ---------------------------------------------------------------------------
// Accurate sincos for |ang| up to ~5000: 3-term Cody-Waite 2*pi reduction
// then MUFU sincos.
// ---------------------------------------------------------------------------
__device__ __forceinline__ void sincos_red(float ang, float* s, float* c) {
    const double TWO_PI_D = 6.283185307179586476925286766559;
    const float  P1 = 6.28125f;
    const float  P2 = (float)(TWO_PI_D - (double)6.28125f);
    const float  P3 = (float)(TWO_PI_D - (double)6.28125f - (double)((float)(TWO_PI_D - (double)6.28125f)));
    const float  INV2PI = 0.15915494309189535f;
    float k = rintf(ang * INV2PI);
    float r = fmaf(-k, P1, ang);
    r = fmaf(-k, P2, r);
    r = fmaf(-k, P3, r);
    __sincosf(r, s, c);
}

// ---------------------------------------------------------------------------
// SINGLE fused kernel, proven R12 structure (192 thr, 4 rows/CTA) with
// compile-time div tables (zero expf in the kernel):
// CHUNK-MAJOR. CTA = (position s, batch-group g); thread t owns float4
// column c=t for rows 4g..4g+3.
//   - word rows: 4 independent LDG.128 issued FIRST (latency overlaps trig)
//   - pe: 2 sincos per thread, divs from const table; pe+type prefolded
//   - hs rows: cooperative into 4KB SMEM (512 sincos / 192 thr)
//   - all elementwise math packed f32x2
// ---------------------------------------------------------------------------
#define RED_ROUND(OFF, K)                                                   \
    {                                                                       \
        _Pragma("unroll")                                                   \
        for (int j = 0; j < (K) / 2; j++) {                                 \
            float send = (lane & (OFF)) ? vals[j] : vals[j + (K) / 2];      \
            float recv = __shfl_xor_sync(0xffffffffu, send, (OFF));         \
            float keep = (lane & (OFF)) ? vals[j + (K) / 2] : vals[j];      \
            vals[j] = keep + recv;                                          \
        }                                                                   \
    }

__global__ __launch_bounds__(192, 6) void emb_ln_kernel(
    const int*   __restrict__ input_ids,     // [8,4096]
    const int*   __restrict__ tok_struct,    // [8,4096,3]
    const int*   __restrict__ token_type,    // [8,4096]
    const float* __restrict__ word_emb,      // [30522,768]
    const float* __restrict__ type_emb,      // [2,768]
    const float* __restrict__ ln_w,          // [768]
    const float* __restrict__ ln_b,          // [768]
    float*       __restrict__ out)           // [8,4096,768]
{
    __shared__ float s_hs[4 * HS_DIM];       // 4 hs rows, (sin,cos) pairs: 4KB
    __shared__ float s_red[6 * 8];           // per-warp reduced (sum0..3, sq0..3)
    __shared__ float s_mu[4], s_rstd[4];

    const int s    = blockIdx.x >> 1;        // position
    const int g    = blockIdx.x & 1;         // batch group: rows 4g..4g+3
    const int tid  = threadIdx.x;
    const int warp = tid >> 5;
    const int lane = tid & 31;
    const int c    = tid;                    // float4 column 0..191
    const int hc   = c & 63;                 // hs float4 column (concat(g,g,g))

    // Row metadata: lanes 0..3 of each warp load (L1-hot), broadcast via shfl.
    int myTok = 0, myTT = 0, myPP = 0;
    if (lane < 4) {
        int idx = (g * 4 + lane) * S_LEN + s;
        myTok = __ldg(&input_ids[idx]);
        myTT  = __ldg(&token_type[idx]);
        myPP  = __ldg(&tok_struct[idx * 3]);
    }
    int ppv[4];
#pragma unroll
    for (int r = 0; r < 4; r++) ppv[r] = __shfl_sync(0xffffffffu, myPP, r);

    // Issue the 4 word-row gathers NOW so their latency overlaps all the trig.
    const float4* w4p = (const float4*)word_emb;
    float4 wv[4];
#pragma unroll
    for (int r = 0; r < 4; r++) {
        int tok = __shfl_sync(0xffffffffu, myTok, r);
        wv[r] = __ldg(w4p + (size_t)tok * 192 + c);
    }

    // pe channels 4c..4c+3: divs from const table (no expf)
    float4 pe4;
    {
        float d0 = __ldg(&g_pe_div.v[2 * c]);
        float d1 = __ldg(&g_pe_div.v[2 * c + 1]);
        sincos_red((float)s * d0, &pe4.x, &pe4.y);
        sincos_red((float)s * d1, &pe4.z, &pe4.w);
    }

    // Cooperative hs rows: 4 rows x 128 freq pairs = 512 tasks over 192 thr.
#pragma unroll
    for (int t = tid; t < 4 * HS_NFREQ; t += 192) {
        int r = t >> 7;
        int k = t & 127;
        float d = __ldg(&g_hs_div.v[k]);
        float sv, cv;
        sincos_red((float)ppv[r] * d, &sv, &cv);
        ((float2*)s_hs)[t] = make_float2(sv, cv);
    }

    // pe + type prefolded into packed pairs (one add2 each, once per thread)
    const float4 t0 = __ldg(((const float4*)type_emb) + c);
    const float4 t1 = __ldg(((const float4*)type_emb) + 192 + c);
    const u64 pe01 = pk2(pe4.x, pe4.y), pe23 = pk2(pe4.z, pe4.w);
    const u64 pt0_01 = add2(pe01, pk2(t0.x, t0.y));
    const u64 pt0_23 = add2(pe23, pk2(t0.z, t0.w));
    const u64 pt1_01 = add2(pe01, pk2(t1.x, t1.y));
    const u64 pt1_23 = add2(pe23, pk2(t1.z, t1.w));

    __syncthreads();

    u64   e01[4], e23[4];
    float vals[8];                           // [sum0..3, sq0..3]
#pragma unroll
    for (int r = 0; r < 4; r++) {
        int tt = __shfl_sync(0xffffffffu, myTT, r);
        float4 h4 = ((const float4*)s_hs)[r * 64 + hc];
        u64 p01 = tt ? pt1_01 : pt0_01;
        u64 p23 = tt ? pt1_23 : pt0_23;
        u64 w01 = pk2(wv[r].x, wv[r].y);
        u64 w23 = pk2(wv[r].z, wv[r].w);
        u64 a01 = add2(add2(w01, pk2(h4.x, h4.y)), p01);
        u64 a23 = add2(add2(w23, pk2(h4.z, h4.w)), p23);
        e01[r] = a01;
        e23[r] = a23;
        float sl, sh, ql, qh;
        upk2(add2(a01, a23), sl, sh);
        vals[r] = sl + sh;
        upk2(fma2(a23, a23, mul2(a01, a01)), ql, qh);
        vals[4 + r] = ql + qh;
    }

    // Value-splitting butterfly: 8 values over 32 lanes.
    RED_ROUND(16, 8)
    RED_ROUND(8, 4)
    RED_ROUND(4, 2)
    vals[0] += __shfl_xor_sync(0xffffffffu, vals[0], 2);
    vals[0] += __shfl_xor_sync(0xffffffffu, vals[0], 1);
    if ((lane & 3) == 0) s_red[warp * 8 + (lane >> 2)] = vals[0];
    __syncthreads();

    if (tid < 4) {
        float sum = 0.f, sq = 0.f;
#pragma unroll
        for (int w = 0; w < 6; w++) {
            sum += s_red[w * 8 + tid];
            sq  += s_red[w * 8 + 4 + tid];
        }
        const float inv_n = 1.0f / 768.0f;
        float mu  = sum * inv_n;
        float var = fmaf(sq, inv_n, -mu * mu);
        var = var < 0.f ? 0.f : var;
        s_mu[tid]   = mu;
        s_rstd[tid] = rsqrtf(var + 1e-12f);
    }
    __syncthreads();

    // ln params loaded after the barrier: not live across the gather loop.
    const float4 wgf = __ldg(((const float4*)ln_w) + c);
    const float4 bif = __ldg(((const float4*)ln_b) + c);
    const u64 wg01 = pk2(wgf.x, wgf.y), wg23 = pk2(wgf.z, wgf.w);
    const u64 bi01 = pk2(bif.x, bif.y), bi23 = pk2(bif.z, bif.w);

    float4* o4 = (float4*)out;
#pragma unroll
    for (int r = 0; r < 4; r++) {
        float mu   = s_mu[r];
        float rstd = s_rstd[r];
        u64 rstd2 = pk2(rstd, rstd);
        u64 nmu2  = pk2(-mu, -mu);
        u64 a01 = mul2(wg01, rstd2);            // wg * rstd
        u64 a23 = mul2(wg23, rstd2);
        u64 b01 = fma2(nmu2, a01, bi01);        // bi - mu*wg*rstd
        u64 b23 = fma2(nmu2, a23, bi23);
        u64 q01 = fma2(e01[r], a01, b01);       // e*(wg*rstd) + b
        u64 q23 = fma2(e23[r], a23, b23);
        float4 o;
        upk2(q01, o.x, o.y);
        upk2(q23, o.z, o.w);
        __stcs(o4 + (size_t)((g * 4 + r) * S_LEN + s) * 192 + c, o);
    }
}

// ---------------------------------------------------------------------------
extern "C" void kernel_launch(void* const* d_in, const int* in_sizes, int n_in,
                              void* d_out, int out_size) {
    const int*   input_ids  = (const int*)  d_in[0];
    const int*   tok_struct = (const int*)  d_in[1];
    // d_in[2] = sent_struct_vec (unused by the reference output)
    const int*   token_type = (const int*)  d_in[3];
    const float* word_emb   = (const float*)d_in[4];
    const float* type_emb   = (const float*)d_in[5];
    const float* ln_w       = (const float*)d_in[6];
    const float* ln_b       = (const float*)d_in[7];
    float*       out        = (float*)d_out;

    emb_ln_kernel<<<S_LEN * 2, 192>>>(input_ids, tok_struct, token_type,
                                      word_emb, type_emb, ln_w, ln_b, out);
}

// round 15
// speedup vs baseline: 1.2378x; 1.1232x over previous
#include <cuda_runtime.h>
#include <math.h>

#define S_LEN    4096
#define B_SZ     8
#define HID      768
#define HS_DIM   256   // HIDDEN/3
#define NFREQ    384   // HID/2
#define HS_NFREQ 128   // HS_DIM/2

typedef unsigned long long u64;

// ---------------------------------------------------------------------------
// Packed f32x2 helpers (sm_103a FADD2/FFMA2; .rn => bit-identical to scalar)
// ---------------------------------------------------------------------------
__device__ __forceinline__ u64 pk2(float lo, float hi) {
    u64 r; asm("mov.b64 %0, {%1, %2};" : "=l"(r) : "f"(lo), "f"(hi)); return r;
}
__device__ __forceinline__ void upk2(u64 v, float& lo, float& hi) {
    asm("mov.b64 {%0, %1}, %2;" : "=f"(lo), "=f"(hi) : "l"(v));
}
__device__ __forceinline__ u64 add2(u64 a, u64 b) {
    u64 r; asm("add.rn.f32x2 %0, %1, %2;" : "=l"(r) : "l"(a), "l"(b)); return r;
}
__device__ __forceinline__ u64 mul2(u64 a, u64 b) {
    u64 r; asm("mul.rn.f32x2 %0, %1, %2;" : "=l"(r) : "l"(a), "l"(b)); return r;
}
__device__ __forceinline__ u64 fma2(u64 a, u64 b, u64 c) {
    u64 r; asm("fma.rn.f32x2 %0, %1, %2, %3;" : "=l"(r) : "l"(a), "l"(b), "l"(c)); return r;
}

// ---------------------------------------------------------------------------
// Compile-time exp tables for the div factors (correctly rounded; >= expf
// accuracy, measured rel_err improves with these).
// ---------------------------------------------------------------------------
constexpr double cexp_d(double x) {
    const double LN2 = 0.6931471805599453094172321214582;
    double q = x / LN2;
    int n = (int)(q - 0.5);
    double r = x - (double)n * LN2;
    double term = 1.0, sum = 1.0;
    for (int i = 1; i < 24; i++) { term *= r / (double)i; sum += term; }
    double sc = 1.0;
    for (int i = 0; i < -n; i++) sc *= 0.5;
    return sum * sc;
}
struct TabPE { float v[NFREQ]; };
struct TabHS { float v[HS_NFREQ]; };
constexpr TabPE make_pe_div() {
    TabPE t{};
    const float CEXP = (float)(-9.210340371976184 / 768.0);
    for (int k = 0; k < NFREQ; k++) t.v[k] = (float)cexp_d((double)((float)(2 * k) * CEXP));
    return t;
}
constexpr TabHS make_hs_div() {
    TabHS t{};
    const float CEXP = (float)(-9.210340371976184 / 256.0);
    for (int k = 0; k < HS_NFREQ; k++) t.v[k] = (float)cexp_d((double)((float)(2 * k) * CEXP));
    return t;
}
__device__ const TabPE g_pe_div = make_pe_div();
__device__ const TabHS g_hs_div = make_hs_div();

// ---------------------------------------------------------------------------
// Accurate sincos for |ang| up to ~5000: 3-term Cody-Waite 2*pi reduction
// then MUFU sincos.
// ---------------------------------------------------------------------------
__device__ __forceinline__ void sincos_red(float ang, float* s, float* c) {
    const double TWO_PI_D = 6.283185307179586476925286766559;
    const float  P1 = 6.28125f;
    const float  P2 = (float)(TWO_PI_D - (double)6.28125f);
    const float  P3 = (float)(TWO_PI_D - (double)6.28125f - (double)((float)(TWO_PI_D - (double)6.28125f)));
    const float  INV2PI = 0.15915494309189535f;
    float k = rintf(ang * INV2PI);
    float r = fmaf(-k, P1, ang);
    r = fmaf(-k, P2, r);
    r = fmaf(-k, P3, r);
    __sincosf(r, s, c);
}

// ---------------------------------------------------------------------------
// SINGLE fused kernel, CHUNK-MAJOR, 8 rows/CTA (one CTA per position):
// thread t owns float4 column c=t for ALL 8 batch rows. Constants (pe, type,
// ln) amortize over 8 rows: ~75 L1 wavefronts/row vs 110 at 4 rows/CTA.
//   - 8 word-row LDG.128 issued first (MLP 8, latency overlaps all trig)
//   - pe: 2 sincos/thread (div from const table), pe+type prefolded
//   - hs: 8 rows x 128 pairs cooperative into 8KB SMEM
//   - packed f32x2 arithmetic; wg/bi loaded after the barrier
//   - launch_bounds(192,5): <=68 regs -> 30 warps/SM
// ---------------------------------------------------------------------------
#define RED_ROUND(OFF, K)                                                   \
    {                                                                       \
        _Pragma("unroll")                                                   \
        for (int j = 0; j < (K) / 2; j++) {                                 \
            float send = (lane & (OFF)) ? vals[j] : vals[j + (K) / 2];      \
            float recv = __shfl_xor_sync(0xffffffffu, send, (OFF));         \
            float keep = (lane & (OFF)) ? vals[j + (K) / 2] : vals[j];      \
            vals[j] = keep + recv;                                          \
        }                                                                   \
    }

__global__ __launch_bounds__(192, 5) void emb_ln_kernel(
    const int*   __restrict__ input_ids,     // [8,4096]
    const int*   __restrict__ tok_struct,    // [8,4096,3]
    const int*   __restrict__ token_type,    // [8,4096]
    const float* __restrict__ word_emb,      // [30522,768]
    const float* __restrict__ type_emb,      // [2,768]
    const float* __restrict__ ln_w,          // [768]
    const float* __restrict__ ln_b,          // [768]
    float*       __restrict__ out)           // [8,4096,768]
{
    __shared__ float s_hs[8 * HS_DIM];       // 8 hs rows: 8KB
    __shared__ float s_red[6 * 16];          // per-warp reduced (sum0..7, sq0..7)
    __shared__ float s_mu[8], s_rstd[8];

    const int s    = blockIdx.x;             // position
    const int tid  = threadIdx.x;
    const int warp = tid >> 5;
    const int lane = tid & 31;
    const int c    = tid;                    // float4 column 0..191
    const int hc   = c & 63;                 // hs float4 column (concat(g,g,g))

    // Row metadata: lanes 0..7 of each warp load (L1-hot), broadcast via shfl.
    int myTok = 0, myTT = 0, myPP = 0;
    if (lane < 8) {
        int idx = lane * S_LEN + s;
        myTok = __ldg(&input_ids[idx]);
        myTT  = __ldg(&token_type[idx]);
        myPP  = __ldg(&tok_struct[idx * 3]);
    }

    // Issue all 8 word-row gathers NOW (MLP 8; latency overlaps all the trig).
    const float4* w4p = (const float4*)word_emb;
    float4 wv[8];
#pragma unroll
    for (int r = 0; r < 8; r++) {
        int tok = __shfl_sync(0xffffffffu, myTok, r);
        wv[r] = __ldg(w4p + (size_t)tok * 192 + c);
    }

    // pe channels 4c..4c+3: divs from const table
    float4 pe4;
    {
        float d0 = __ldg(&g_pe_div.v[2 * c]);
        float d1 = __ldg(&g_pe_div.v[2 * c + 1]);
        sincos_red((float)s * d0, &pe4.x, &pe4.y);
        sincos_red((float)s * d1, &pe4.z, &pe4.w);
    }

    // Cooperative hs rows: 8 rows x 128 freq pairs = 1024 tasks / 192 thr.
    {
        int pp0 = __shfl_sync(0xffffffffu, myPP, 0);
        int pp1 = __shfl_sync(0xffffffffu, myPP, 1);
        int pp2 = __shfl_sync(0xffffffffu, myPP, 2);
        int pp3 = __shfl_sync(0xffffffffu, myPP, 3);
        int pp4 = __shfl_sync(0xffffffffu, myPP, 4);
        int pp5 = __shfl_sync(0xffffffffu, myPP, 5);
        int pp6 = __shfl_sync(0xffffffffu, myPP, 6);
        int pp7 = __shfl_sync(0xffffffffu, myPP, 7);
#pragma unroll
        for (int t = tid; t < 8 * HS_NFREQ; t += 192) {
            int r8 = t >> 7;
            int k  = t & 127;
            int pp = r8 < 4 ? (r8 < 2 ? (r8 == 0 ? pp0 : pp1) : (r8 == 2 ? pp2 : pp3))
                            : (r8 < 6 ? (r8 == 4 ? pp4 : pp5) : (r8 == 6 ? pp6 : pp7));
            float d = __ldg(&g_hs_div.v[k]);
            float sv, cv;
            sincos_red((float)pp * d, &sv, &cv);
            ((float2*)s_hs)[t] = make_float2(sv, cv);
        }
    }

    // pe + type prefolded into packed pairs (once per thread, 8-row amortized)
    const float4 t0 = __ldg(((const float4*)type_emb) + c);
    const float4 t1 = __ldg(((const float4*)type_emb) + 192 + c);
    const u64 pe01 = pk2(pe4.x, pe4.y), pe23 = pk2(pe4.z, pe4.w);
    const u64 pt0_01 = add2(pe01, pk2(t0.x, t0.y));
    const u64 pt0_23 = add2(pe23, pk2(t0.z, t0.w));
    const u64 pt1_01 = add2(pe01, pk2(t1.x, t1.y));
    const u64 pt1_23 = add2(pe23, pk2(t1.z, t1.w));

    __syncthreads();

    u64   e01[8], e23[8];
    float vals[16];                          // [sum0..7, sq0..7]
#pragma unroll
    for (int r = 0; r < 8; r++) {
        int tt = __shfl_sync(0xffffffffu, myTT, r);
        float4 h4 = ((const float4*)s_hs)[r * 64 + hc];
        u64 p01 = tt ? pt1_01 : pt0_01;
        u64 p23 = tt ? pt1_23 : pt0_23;
        u64 a01 = add2(add2(pk2(wv[r].x, wv[r].y), pk2(h4.x, h4.y)), p01);
        u64 a23 = add2(add2(pk2(wv[r].z, wv[r].w), pk2(h4.z, h4.w)), p23);
        e01[r] = a01;
        e23[r] = a23;
        float sl, sh, ql, qh;
        upk2(add2(a01, a23), sl, sh);
        vals[r] = sl + sh;
        upk2(fma2(a23, a23, mul2(a01, a01)), ql, qh);
        vals[8 + r] = ql + qh;
    }

    // Value-splitting butterfly: 16 values over 32 lanes in 16 shfl.
    RED_ROUND(16, 16)
    RED_ROUND(8, 8)
    RED_ROUND(4, 4)
    RED_ROUND(2, 2)
    vals[0] += __shfl_xor_sync(0xffffffffu, vals[0], 1);
    // Lane L (even) holds reduced value index (L>>1)&15.
    if (!(lane & 1)) s_red[warp * 16 + ((lane >> 1) & 15)] = vals[0];
    __syncthreads();

    if (tid < 8) {
        float sum = 0.f, sq = 0.f;
#pragma unroll
        for (int w = 0; w < 6; w++) {
            sum += s_red[w * 16 + tid];
            sq  += s_red[w * 16 + 8 + tid];
        }
        const float inv_n = 1.0f / 768.0f;
        float mu  = sum * inv_n;
        float var = fmaf(sq, inv_n, -mu * mu);
        var = var < 0.f ? 0.f : var;
        s_mu[tid]   = mu;
        s_rstd[tid] = rsqrtf(var + 1e-12f);
    }
    __syncthreads();

    // ln params loaded after the barrier: not live across the gather loop.
    const float4 wgf = __ldg(((const float4*)ln_w) + c);
    const float4 bif = __ldg(((const float4*)ln_b) + c);
    const u64 wg01 = pk2(wgf.x, wgf.y), wg23 = pk2(wgf.z, wgf.w);
    const u64 bi01 = pk2(bif.x, bif.y), bi23 = pk2(bif.z, bif.w);

    float4* o4 = (float4*)out;
#pragma unroll
    for (int r = 0; r < 8; r++) {
        float mu   = s_mu[r];
        float rstd = s_rstd[r];
        u64 rstd2 = pk2(rstd, rstd);
        u64 nmu2  = pk2(-mu, -mu);
        u64 a01 = mul2(wg01, rstd2);            // wg * rstd
        u64 a23 = mul2(wg23, rstd2);
        u64 b01 = fma2(nmu2, a01, bi01);        // bi - mu*wg*rstd
        u64 b23 = fma2(nmu2, a23, bi23);
        u64 q01 = fma2(e01[r], a01, b01);       // e*(wg*rstd) + b
        u64 q23 = fma2(e23[r], a23, b23);
        float4 o;
        upk2(q01, o.x, o.y);
        upk2(q23, o.z, o.w);
        __stcs(o4 + (size_t)(r * S_LEN + s) * 192 + c, o);
    }
}

// ---------------------------------------------------------------------------
extern "C" void kernel_launch(void* const* d_in, const int* in_sizes, int n_in,
                              void* d_out, int out_size) {
    const int*   input_ids  = (const int*)  d_in[0];
    const int*   tok_struct = (const int*)  d_in[1];
    // d_in[2] = sent_struct_vec (unused by the reference output)
    const int*   token_type = (const int*)  d_in[3];
    const float* word_emb   = (const float*)d_in[4];
    const float* type_emb   = (const float*)d_in[5];
    const float* ln_w       = (const float*)d_in[6];
    const float* ln_b       = (const float*)d_in[7];
    float*       out        = (float*)d_out;

    emb_ln_kernel<<<S_LEN, 192>>>(input_ids, tok_struct, token_type,
                                  word_emb, type_emb, ln_w, ln_b, out);
}